// round 2
// baseline (speedup 1.0000x reference)
#include <cuda_runtime.h>

#define Bn 256
#define Tn 2048
#define Dn 64
#define LBn 2
#define DBn 32
#define Ln 2
#define Gn 96

// static scratch: compacted dt per (b, band), and counts
__device__ float g_dts[Bn * LBn * Tn];
__device__ int   g_cnt[Bn * LBn];

// ---------------------------------------------------------------------------
// Prep: stable compaction of dtime per (row, band) via block prefix scan.
// band values are {0,1}: one inclusive scan of ones serves both bands.
// ---------------------------------------------------------------------------
__global__ void prep_kernel(const int* __restrict__ band_ids,
                            const float* __restrict__ dtime) {
    const int b = blockIdx.x;
    const int tid = threadIdx.x;  // 256 threads, 8 elems each
    __shared__ int s_scan[256];

    int loc[8];
    int cnt = 0;
    const int base = b * Tn + tid * 8;
#pragma unroll
    for (int k = 0; k < 8; k++) { loc[k] = band_ids[base + k]; cnt += loc[k]; }
    s_scan[tid] = cnt;
    __syncthreads();

    // Hillis-Steele inclusive scan over 256 partials
    for (int off = 1; off < 256; off <<= 1) {
        int v = s_scan[tid];
        int w = (tid >= off) ? s_scan[tid - off] : 0;
        __syncthreads();
        s_scan[tid] = v + w;
        __syncthreads();
    }
    const int total = s_scan[255];
    int ones_before = s_scan[tid] - cnt;  // exclusive prefix of ones

#pragma unroll
    for (int k = 0; k < 8; k++) {
        int t = tid * 8 + k;
        int bid = loc[k];
        int pos = bid ? ones_before : (t - ones_before);
        g_dts[(b * LBn + bid) * Tn + pos] = dtime[b * Tn + t];
        ones_before += bid;
    }
    if (tid == 0) {
        g_cnt[b * LBn + 1] = total;
        g_cnt[b * LBn + 0] = Tn - total;
    }
}

// ---------------------------------------------------------------------------
// Main: one block (96 threads) per (row, band) chain.
// Thread g owns rows g of Whh(l1), Wih(l2), Whh(l2) in registers.
// h1/h2 in smem (broadcast reads). gx1 collapses to gbase + dt*gw.
// ---------------------------------------------------------------------------
__global__ __launch_bounds__(96)
void rnn_kernel(const float* __restrict__ zlast,
                const float* __restrict__ projW, const float* __restrict__ projB,
                const float* __restrict__ Wih,   const float* __restrict__ Whh,
                const float* __restrict__ bih,   const float* __restrict__ bhh,
                const float* __restrict__ mW1,   const float* __restrict__ mb1,
                const float* __restrict__ mW2,   const float* __restrict__ mb2,
                float* __restrict__ out) {
    const int kb = blockIdx.x & 1;
    const int b  = blockIdx.x >> 1;
    const int g  = threadIdx.x;   // 0..95
    const int lane = g & 31;
    const int warp = g >> 5;

    __shared__ float sH1[32], sH2[32];
    __shared__ float sGH[96], sGX[96];
    __shared__ float sBase[32], sW[32];
    __shared__ float sZ[64];
    __shared__ float sMW1[32 * 32];
    __shared__ float sMW2[32], sMB1[32];
    __shared__ float sDT[Tn];
    __shared__ float sLastY;

    const int cid = b * LBn + kb;

    if (g < 64) sZ[g] = zlast[b * Dn + g];
    for (int i = g; i < 32 * 32; i += 96) sMW1[i] = mW1[kb * 32 * 32 + i];
    if (g < 32) {
        sMW2[g] = mW2[kb * 32 + g];
        sMB1[g] = mb1[kb * 32 + g];
        sH1[g] = 0.f; sH2[g] = 0.f;
    }
    for (int i = g; i < Tn; i += 96) sDT[i] = g_dts[cid * Tn + i];

    const int l1off = (kb * Ln + 0) * Gn;
    const int l2off = (kb * Ln + 1) * Gn;

    float wh1[32], wi2[32], wh2[32];
#pragma unroll
    for (int d = 0; d < 32; d++) {
        wh1[d] = Whh[(l1off + g) * DBn + d];
        wi2[d] = Wih[(l2off + g) * DBn + d];
        wh2[d] = Whh[(l2off + g) * DBn + d];
    }
    const float bhh1 = bhh[l1off + g];
    const float bih2 = bih[l2off + g];
    const float bhh2 = bhh[l2off + g];
    const float mb2v = mb2[kb];

    __syncthreads();

    // per-chain input projection: x_t = base + dt_t * w   (threads 0..31)
    if (g < 32) {
        float acc = projB[kb * DBn + g];
#pragma unroll
        for (int i = 0; i < 64; i++)
            acc += sZ[i] * projW[(kb * (Dn + 1) + i) * DBn + g];
        sBase[g] = acc;
        sW[g] = projW[(kb * (Dn + 1) + Dn) * DBn + g];
    }
    __syncthreads();

    // collapse layer-1 input gates: gx1(t) = gbase + dt * gw
    float gbase = bih[l1off + g];
    float gw = 0.f;
#pragma unroll
    for (int d = 0; d < 32; d++) {
        float w = Wih[(l1off + g) * DBn + d];
        gbase += w * sBase[d];
        gw    += w * sW[d];
    }

    const int n = g_cnt[cid];
    float* outp = out + (size_t)(kb * Bn + b) * Tn;

    // lastY for the n==0 case: MLP(h2 = 0)
    if (warp == 0) {
        float m = fmaxf(sMB1[lane], 0.f);
        float y = m * sMW2[lane];
#pragma unroll
        for (int o = 16; o > 0; o >>= 1) y += __shfl_xor_sync(0xffffffffu, y, o);
        if (lane == 0) sLastY = y + mb2v;
    }
    __syncthreads();

    float h1 = 0.f, h2 = 0.f;  // state lives in lanes of warp responsibility (g<32)

    for (int i = 0; i < n; i++) {
        const float dt = sDT[i];
        // Phase A: gh1 (96x32 matvec, register weights) + gx1 (2 FMA)
        {
            float a0 = 0, a1 = 0, a2 = 0, a3 = 0;
            const float4* hv = (const float4*)sH1;
#pragma unroll
            for (int k = 0; k < 8; k++) {
                float4 h = hv[k];
                a0 += wh1[4 * k + 0] * h.x; a1 += wh1[4 * k + 1] * h.y;
                a2 += wh1[4 * k + 2] * h.z; a3 += wh1[4 * k + 3] * h.w;
            }
            sGH[g] = bhh1 + ((a0 + a1) + (a2 + a3));
            sGX[g] = gbase + dt * gw;
        }
        __syncthreads();
        // Phase B: h1 gate update (threads 0..31)
        if (g < 32) {
            float r  = 1.f / (1.f + __expf(-(sGX[g] + sGH[g])));
            float z  = 1.f / (1.f + __expf(-(sGX[32 + g] + sGH[32 + g])));
            float nn = tanhf(sGX[64 + g] + r * sGH[64 + g]);
            h1 = (1.f - z) * nn + z * h1;
            sH1[g] = h1;
        }
        __syncthreads();
        // Phase C: gh2 + gx2 (two 96x32 matvecs)
        {
            float a0 = 0, a1 = 0, a2 = 0, a3 = 0;
            float c0 = 0, c1 = 0, c2 = 0, c3 = 0;
            const float4* xv = (const float4*)sH1;
            const float4* hv = (const float4*)sH2;
#pragma unroll
            for (int k = 0; k < 8; k++) {
                float4 x = xv[k]; float4 h = hv[k];
                a0 += wi2[4 * k + 0] * x.x; a1 += wi2[4 * k + 1] * x.y;
                a2 += wi2[4 * k + 2] * x.z; a3 += wi2[4 * k + 3] * x.w;
                c0 += wh2[4 * k + 0] * h.x; c1 += wh2[4 * k + 1] * h.y;
                c2 += wh2[4 * k + 2] * h.z; c3 += wh2[4 * k + 3] * h.w;
            }
            sGX[g] = bih2 + ((a0 + a1) + (a2 + a3));
            sGH[g] = bhh2 + ((c0 + c1) + (c2 + c3));
        }
        __syncthreads();
        // Phase D: h2 gate update
        if (g < 32) {
            float r  = 1.f / (1.f + __expf(-(sGX[g] + sGH[g])));
            float z  = 1.f / (1.f + __expf(-(sGX[32 + g] + sGH[32 + g])));
            float nn = tanhf(sGX[64 + g] + r * sGH[64 + g]);
            h2 = (1.f - z) * nn + z * h2;
            sH2[g] = h2;
        }
        __syncthreads();
        // Phase E: MLP head on warp 0 (overlaps next Phase A of warps 1,2)
        if (warp == 0) {
            float m = sMB1[lane];
#pragma unroll
            for (int e = 0; e < 32; e++) m += sH2[e] * sMW1[e * 32 + lane];
            m = fmaxf(m, 0.f);
            float y = m * sMW2[lane];
#pragma unroll
            for (int o = 16; o > 0; o >>= 1) y += __shfl_xor_sync(0xffffffffu, y, o);
            if (lane == 0) { float yy = y + mb2v; outp[i] = yy; sLastY = yy; }
        }
    }
    __syncthreads();
    const float ylast = sLastY;
    for (int i = n + g; i < Tn; i += 96) outp[i] = ylast;
}

extern "C" void kernel_launch(void* const* d_in, const int* in_sizes, int n_in,
                              void* d_out, int out_size) {
    const int*   band_ids = (const int*)  d_in[0];
    const float* dtime    = (const float*)d_in[1];
    const float* zlast    = (const float*)d_in[2];
    const float* projW    = (const float*)d_in[3];
    const float* projB    = (const float*)d_in[4];
    const float* Wih      = (const float*)d_in[5];
    const float* Whh      = (const float*)d_in[6];
    const float* bihp     = (const float*)d_in[7];
    const float* bhhp     = (const float*)d_in[8];
    const float* mW1      = (const float*)d_in[9];
    const float* mb1      = (const float*)d_in[10];
    const float* mW2      = (const float*)d_in[11];
    const float* mb2      = (const float*)d_in[12];

    prep_kernel<<<Bn, 256>>>(band_ids, dtime);
    rnn_kernel<<<Bn * LBn, 96>>>(zlast, projW, projB, Wih, Whh, bihp, bhhp,
                                 mW1, mb1, mW2, mb2, (float*)d_out);
}

// round 4
// speedup vs baseline: 1.0131x; 1.0131x over previous
#include <cuda_runtime.h>

#define Bn 256
#define Tn 2048
#define Dn 64
#define LBn 2
#define DBn 32
#define Gn 96
#define Ln 2
#define CH 8      // steps per chunk
#define RD 4      // ring depth in chunks

__device__ float g_dts[Bn * LBn * Tn];
__device__ int   g_cnt[Bn * LBn];

typedef unsigned long long u64;

__device__ __forceinline__ u64 ffma2(u64 a, u64 b, u64 c) {
    u64 d; asm("fma.rn.f32x2 %0,%1,%2,%3;" : "=l"(d) : "l"(a), "l"(b), "l"(c)); return d;
}
__device__ __forceinline__ float ex2f(float x) { float y; asm("ex2.approx.f32 %0,%1;" : "=f"(y) : "f"(x)); return y; }
__device__ __forceinline__ float rcpf(float x) { float y; asm("rcp.approx.f32 %0,%1;" : "=f"(y) : "f"(x)); return y; }
__device__ __forceinline__ int ldacq(const int* p) {
    int v; asm volatile("ld.acquire.cta.b32 %0,[%1];" : "=r"(v) : "l"(p) : "memory"); return v;
}
__device__ __forceinline__ void strel(int* p, int v) {
    asm volatile("st.release.cta.b32 [%0],%1;" :: "l"(p), "r"(v) : "memory");
}

union F2 { float2 f; u64 u; };
__device__ __forceinline__ u64 pack2(float a, float b) { F2 t; t.f = make_float2(a, b); return t.u; }
__device__ __forceinline__ float hsum(u64 a) { F2 t; t.u = a; return t.f.x + t.f.y; }

__device__ __forceinline__ float dot32(const u64* w, const u64* hp) {
    u64 a0 = 0ull, a1 = 0ull;
#pragma unroll
    for (int k = 0; k < 16; k += 2) { a0 = ffma2(w[k], hp[k], a0); a1 = ffma2(w[k + 1], hp[k + 1], a1); }
    return hsum(a0) + hsum(a1);
}
__device__ __forceinline__ void loadrow(u64* w, const float* p, float s) {
#pragma unroll
    for (int k = 0; k < 16; k++) w[k] = pack2(p[2 * k] * s, p[2 * k + 1] * s);
}

// ---------------------------------------------------------------------------
// Prep: stable compaction of dtime per (row, band) via block prefix scan.
// ---------------------------------------------------------------------------
__global__ void prep_kernel(const int* __restrict__ band_ids,
                            const float* __restrict__ dtime) {
    const int b = blockIdx.x;
    const int tid = threadIdx.x;
    __shared__ int s_scan[256];

    int loc[8]; int cnt = 0;
    const int base = b * Tn + tid * 8;
#pragma unroll
    for (int k = 0; k < 8; k++) { loc[k] = band_ids[base + k]; cnt += loc[k]; }
    s_scan[tid] = cnt;
    __syncthreads();
    for (int off = 1; off < 256; off <<= 1) {
        int v = s_scan[tid];
        int w = (tid >= off) ? s_scan[tid - off] : 0;
        __syncthreads();
        s_scan[tid] = v + w;
        __syncthreads();
    }
    const int total = s_scan[255];
    int ones_before = s_scan[tid] - cnt;
#pragma unroll
    for (int k = 0; k < 8; k++) {
        int t = tid * 8 + k;
        int bid = loc[k];
        int pos = bid ? ones_before : (t - ones_before);
        g_dts[(b * LBn + bid) * Tn + pos] = dtime[b * Tn + t];
        ones_before += bid;
    }
    if (tid == 0) {
        g_cnt[b * LBn + 1] = total;
        g_cnt[b * LBn + 0] = Tn - total;
    }
}

// ---------------------------------------------------------------------------
// Main: one block (3 warps) per chain, layer-pipelined.
//   W0: layer-1 recurrence -> sH1 ring
//   W2: gx2 = Wih2 @ h1 (feedforward) -> sGX2 ring ; MLP on sH2 ; tail fill
//   W1: layer-2 recurrence (gh2 + gx2) -> sH2 ring
// ---------------------------------------------------------------------------
__global__ void __launch_bounds__(96, 4)
rnn_kernel(const float* __restrict__ zlast,
           const float* __restrict__ projW, const float* __restrict__ projB,
           const float* __restrict__ Wih,   const float* __restrict__ Whh,
           const float* __restrict__ bih,   const float* __restrict__ bhh,
           const float* __restrict__ mW1,   const float* __restrict__ mb1,
           const float* __restrict__ mW2,   const float* __restrict__ mb2,
           float* __restrict__ out) {
    const int kb = blockIdx.x & 1;
    const int b  = blockIdx.x >> 1;
    const int g  = threadIdx.x;
    const int lane = g & 31;
    const int warp = g >> 5;
    const int cid = b * LBn + kb;

    __shared__ __align__(16) float sDT[Tn];
    __shared__ __align__(16) float sH1[RD][CH][32];
    __shared__ __align__(16) float sGX2[RD][CH][96];
    __shared__ __align__(16) float sH2[RD][CH][32];
    __shared__ __align__(16) u64   sMW1p[16 * 32];   // packed mW1 column pairs
    __shared__ float sBase[32], sW[32], sZ[64];
    __shared__ int f_h1, f_gx2, f_h2, f_mlp;

    for (int i = g; i < Tn; i += 96) sDT[i] = g_dts[cid * Tn + i];
    if (g < 64) sZ[g] = zlast[b * Dn + g];
    if (g == 0) { f_h1 = 0; f_gx2 = 0; f_h2 = 0; f_mlp = 0; }
    for (int idx = g; idx < 16 * 32; idx += 96) {
        int k = idx >> 5, d = idx & 31;
        sMW1p[idx] = pack2(mW1[kb * 1024 + (2 * k) * 32 + d],
                           mW1[kb * 1024 + (2 * k + 1) * 32 + d]);
    }
    __syncthreads();

    const int n = g_cnt[cid];
    const int nch = (n + CH - 1) / CH;
    float* outp = out + (size_t)(kb * Bn + b) * Tn;
    const float s1 = -1.4426950408889634f;   // -log2(e)
    const float s2 = -2.8853900817779268f;   // -2*log2(e)
    const int l1 = (kb * Ln + 0) * Gn;
    const int l2 = (kb * Ln + 1) * Gn;

    if (warp == 0) {
        // -------- layer-1 recurrence --------
        u64 wr[16], wz[16], wn[16];
        loadrow(wr, &Whh[(l1 + lane) * DBn], s1);
        loadrow(wz, &Whh[(l1 + lane + 32) * DBn], s1);
        loadrow(wn, &Whh[(l1 + lane + 64) * DBn], s2);
        const float bhr = s1 * bhh[l1 + lane];
        const float bhz = s1 * bhh[l1 + lane + 32];
        const float bhn = s2 * bhh[l1 + lane + 64];

        // input projection base: x_t = base + dt*w
        float base = projB[kb * DBn + lane];
        float w = projW[(kb * (Dn + 1) + Dn) * DBn + lane];
#pragma unroll 8
        for (int i = 0; i < 64; i++) base += sZ[i] * projW[(kb * (Dn + 1) + i) * DBn + lane];
        sBase[lane] = base; sW[lane] = w;
        __syncwarp();

        float gbr, gbz, gbn, gwr, gwz, gwn;
        {
            float ar = bih[l1 + lane], cr = 0.f;
            float az = bih[l1 + lane + 32], cz = 0.f;
            float an = bih[l1 + lane + 64], cn = 0.f;
#pragma unroll 8
            for (int d = 0; d < 32; d++) {
                float wv = Wih[(l1 + lane) * DBn + d];
                ar += wv * sBase[d]; cr += wv * sW[d];
                wv = Wih[(l1 + lane + 32) * DBn + d];
                az += wv * sBase[d]; cz += wv * sW[d];
                wv = Wih[(l1 + lane + 64) * DBn + d];
                an += wv * sBase[d]; cn += wv * sW[d];
            }
            gbr = s1 * ar; gwr = s1 * cr;
            gbz = s1 * az; gwz = s1 * cz;
            gbn = s2 * an; gwn = s2 * cn;
        }

        float h1s = 0.f;
        u64 hp[16];
#pragma unroll
        for (int k = 0; k < 16; k++) hp[k] = 0ull;

        for (int c = 0; c < nch; c++) {
            if (c >= RD) while (ldacq(&f_gx2) < c - (RD - 1)) {}
#pragma unroll
            for (int i = 0; i < CH; i++) {
                const float dt = sDT[c * CH + i];
                float ghr = bhr + dot32(wr, hp);
                float ghz = bhz + dot32(wz, hp);
                float ghn = bhn + dot32(wn, hp);
                float gxr = fmaf(dt, gwr, gbr);
                float gxz = fmaf(dt, gwz, gbz);
                float gxn = fmaf(dt, gwn, gbn);
                float r  = rcpf(1.f + ex2f(gxr + ghr));
                float z  = rcpf(1.f + ex2f(gxz + ghz));
                float nn = fmaf(2.f, rcpf(1.f + ex2f(fmaf(r, ghn, gxn))), -1.f);
                h1s = fmaf(z, h1s - nn, nn);
                sH1[c & 3][i][lane] = h1s;
                __syncwarp();
                const u64* hv = (const u64*)sH1[c & 3][i];
#pragma unroll
                for (int k = 0; k < 16; k++) hp[k] = hv[k];
            }
            if (lane == 0) strel(&f_h1, c + 1);
        }
    } else if (warp == 1) {
        // -------- layer-2 recurrence --------
        u64 wr[16], wz[16], wn[16];
        loadrow(wr, &Whh[(l2 + lane) * DBn], s1);
        loadrow(wz, &Whh[(l2 + lane + 32) * DBn], s1);
        loadrow(wn, &Whh[(l2 + lane + 64) * DBn], s2);
        const float bhr = s1 * bhh[l2 + lane];
        const float bhz = s1 * bhh[l2 + lane + 32];
        const float bhn = s2 * bhh[l2 + lane + 64];

        float h2s = 0.f;
        u64 hp[16];
#pragma unroll
        for (int k = 0; k < 16; k++) hp[k] = 0ull;

        for (int c = 0; c < nch; c++) {
            while (ldacq(&f_gx2) < c + 1) {}
            if (c >= RD) while (ldacq(&f_mlp) < c - (RD - 1)) {}
#pragma unroll
            for (int i = 0; i < CH; i++) {
                float gxr = sGX2[c & 3][i][lane];
                float gxz = sGX2[c & 3][i][lane + 32];
                float gxn = sGX2[c & 3][i][lane + 64];
                float ghr = bhr + dot32(wr, hp);
                float ghz = bhz + dot32(wz, hp);
                float ghn = bhn + dot32(wn, hp);
                float r  = rcpf(1.f + ex2f(gxr + ghr));
                float z  = rcpf(1.f + ex2f(gxz + ghz));
                float nn = fmaf(2.f, rcpf(1.f + ex2f(fmaf(r, ghn, gxn))), -1.f);
                h2s = fmaf(z, h2s - nn, nn);
                sH2[c & 3][i][lane] = h2s;
                __syncwarp();
                const u64* hv = (const u64*)sH2[c & 3][i];
#pragma unroll
                for (int k = 0; k < 16; k++) hp[k] = hv[k];
            }
            if (lane == 0) strel(&f_h2, c + 1);
        }
    } else {
        // -------- feedforward: gx2 producer + MLP consumer + tail --------
        u64 wr[16], wz[16], wn[16];
        loadrow(wr, &Wih[(l2 + lane) * DBn], s1);
        loadrow(wz, &Wih[(l2 + lane + 32) * DBn], s1);
        loadrow(wn, &Wih[(l2 + lane + 64) * DBn], s2);
        const float bir = s1 * bih[l2 + lane];
        const float biz = s1 * bih[l2 + lane + 32];
        const float bin = s2 * bih[l2 + lane + 64];
        const float mb1v = mb1[kb * DBn + lane];
        const float mw2v = mW2[kb * DBn + lane];
        const float mb2v = mb2[kb];
        float yl = 0.f;

        for (int c = 0; c < nch; c++) {
            while (ldacq(&f_h1) < c + 1) {}
            if (c >= RD) while (ldacq(&f_h2) < c - (RD - 1)) {}
#pragma unroll
            for (int i = 0; i < CH; i++) {
                const u64* hv = (const u64*)sH1[c & 3][i];
                u64 hp[16];
#pragma unroll
                for (int k = 0; k < 16; k++) hp[k] = hv[k];
                sGX2[c & 3][i][lane]      = bir + dot32(wr, hp);
                sGX2[c & 3][i][lane + 32] = biz + dot32(wz, hp);
                sGX2[c & 3][i][lane + 64] = bin + dot32(wn, hp);
            }
            __syncwarp();
            if (lane == 0) strel(&f_gx2, c + 1);

            if (c >= 1) {
                const int cc = c - 1;
                while (ldacq(&f_h2) < cc + 1) {}
#pragma unroll
                for (int i = 0; i < CH; i++) {
                    const int t = cc * CH + i;
                    const u64* hv = (const u64*)sH2[cc & 3][i];
                    u64 a0 = 0ull, a1 = 0ull;
#pragma unroll
                    for (int k = 0; k < 16; k += 2) {
                        a0 = ffma2(sMW1p[k * 32 + lane], hv[k], a0);
                        a1 = ffma2(sMW1p[(k + 1) * 32 + lane], hv[k + 1], a1);
                    }
                    float m = fmaxf(hsum(a0) + hsum(a1) + mb1v, 0.f);
                    float y = m * mw2v;
#pragma unroll
                    for (int off = 16; off > 0; off >>= 1) y += __shfl_xor_sync(0xffffffffu, y, off);
                    y += mb2v;
                    if (lane == 0 && t < n) outp[t] = y;
                    if (t == n - 1) yl = y;
                }
                if (lane == 0) strel(&f_mlp, cc + 1);
            }
        }
        if (nch >= 1) {
            const int cc = nch - 1;
            while (ldacq(&f_h2) < cc + 1) {}
#pragma unroll
            for (int i = 0; i < CH; i++) {
                const int t = cc * CH + i;
                const u64* hv = (const u64*)sH2[cc & 3][i];
                u64 a0 = 0ull, a1 = 0ull;
#pragma unroll
                for (int k = 0; k < 16; k += 2) {
                    a0 = ffma2(sMW1p[k * 32 + lane], hv[k], a0);
                    a1 = ffma2(sMW1p[(k + 1) * 32 + lane], hv[k + 1], a1);
                }
                float m = fmaxf(hsum(a0) + hsum(a1) + mb1v, 0.f);
                float y = m * mw2v;
#pragma unroll
                for (int off = 16; off > 0; off >>= 1) y += __shfl_xor_sync(0xffffffffu, y, off);
                y += mb2v;
                if (lane == 0 && t < n) outp[t] = y;
                if (t == n - 1) yl = y;
            }
            if (lane == 0) strel(&f_mlp, cc + 1);
        }
        if (n == 0) {
            float m = fmaxf(mb1v, 0.f);
            float y = m * mw2v;
#pragma unroll
            for (int off = 16; off > 0; off >>= 1) y += __shfl_xor_sync(0xffffffffu, y, off);
            yl = y + mb2v;
        }
        for (int t = n + lane; t < Tn; t += 32) outp[t] = yl;
    }
}

extern "C" void kernel_launch(void* const* d_in, const int* in_sizes, int n_in,
                              void* d_out, int out_size) {
    const int*   band_ids = (const int*)  d_in[0];
    const float* dtime    = (const float*)d_in[1];
    const float* zlast    = (const float*)d_in[2];
    const float* projW    = (const float*)d_in[3];
    const float* projB    = (const float*)d_in[4];
    const float* Wih      = (const float*)d_in[5];
    const float* Whh      = (const float*)d_in[6];
    const float* bihp     = (const float*)d_in[7];
    const float* bhhp     = (const float*)d_in[8];
    const float* mW1      = (const float*)d_in[9];
    const float* mb1      = (const float*)d_in[10];
    const float* mW2      = (const float*)d_in[11];
    const float* mb2      = (const float*)d_in[12];

    prep_kernel<<<Bn, 256>>>(band_ids, dtime);
    rnn_kernel<<<Bn * LBn, 96>>>(zlast, projW, projB, Wih, Whh, bihp, bhhp,
                                 mW1, mb1, mW2, mb2, (float*)d_out);
}

// round 6
// speedup vs baseline: 2.0913x; 2.0643x over previous
#include <cuda_runtime.h>

#define Bn 256
#define Tn 2048
#define Dn 64
#define LBn 2
#define DBn 32
#define Gn 96
#define Ln 2
#define CH 8      // steps per chunk
#define RD 2      // ring depth in chunks (per-slot named barriers)

__device__ float g_dts[Bn * LBn * Tn];
__device__ int   g_cnt[Bn * LBn];

typedef unsigned long long u64;

__device__ __forceinline__ u64 ffma2(u64 a, u64 b, u64 c) {
    u64 d; asm("fma.rn.f32x2 %0,%1,%2,%3;" : "=l"(d) : "l"(a), "l"(b), "l"(c)); return d;
}
__device__ __forceinline__ float ex2f(float x) { float y; asm("ex2.approx.f32 %0,%1;" : "=f"(y) : "f"(x)); return y; }
__device__ __forceinline__ float rcpf(float x) { float y; asm("rcp.approx.f32 %0,%1;" : "=f"(y) : "f"(x)); return y; }

__device__ __forceinline__ void bar_sync(int id) {
    asm volatile("bar.sync %0, 64;" :: "r"(id) : "memory");
}
__device__ __forceinline__ void bar_arrive(int id) {
    asm volatile("bar.arrive %0, 64;" :: "r"(id) : "memory");
}
__device__ __forceinline__ void membar_cta() {
    asm volatile("membar.cta;" ::: "memory");
}
__device__ __forceinline__ void cbar() { asm volatile("" ::: "memory"); }

// named barrier ids (count=64: one producer warp + one consumer warp)
#define B_R1 1   // +slot: W0 -> W2  (sH1 ready)
#define B_S1 3   // +slot: W2 -> W0  (sH1 slot free)
#define B_R2 5   // +slot: W2 -> W1  (sGX2 ready)
#define B_R3 7   // +slot: W1 -> W2  (sH2 ready; also implies sGX2 slot free)
#define B_S2 9   // +slot: W2 -> W1  (sH2 slot free)

union F2 { float2 f; u64 u; };
__device__ __forceinline__ u64 pack2(float a, float b) { F2 t; t.f = make_float2(a, b); return t.u; }
__device__ __forceinline__ float hsum(u64 a) { F2 t; t.u = a; return t.f.x + t.f.y; }

__device__ __forceinline__ float dot32(const u64* w, const u64* hp) {
    u64 a0 = 0ull, a1 = 0ull;
#pragma unroll
    for (int k = 0; k < 16; k += 2) { a0 = ffma2(w[k], hp[k], a0); a1 = ffma2(w[k + 1], hp[k + 1], a1); }
    return hsum(a0) + hsum(a1);
}
__device__ __forceinline__ void loadrow(u64* w, const float* p, float s) {
#pragma unroll
    for (int k = 0; k < 16; k++) w[k] = pack2(p[2 * k] * s, p[2 * k + 1] * s);
}
__device__ __forceinline__ void loadhp(u64* hp, const float* row) {
    const ulonglong2* hv = (const ulonglong2*)row;
#pragma unroll
    for (int k = 0; k < 8; k++) { ulonglong2 v = hv[k]; hp[2 * k] = v.x; hp[2 * k + 1] = v.y; }
}

// ---------------------------------------------------------------------------
// Prep: stable compaction of dtime per (row, band) via block prefix scan.
// ---------------------------------------------------------------------------
__global__ void prep_kernel(const int* __restrict__ band_ids,
                            const float* __restrict__ dtime) {
    const int b = blockIdx.x;
    const int tid = threadIdx.x;
    __shared__ int s_scan[256];

    int loc[8]; int cnt = 0;
    const int base = b * Tn + tid * 8;
#pragma unroll
    for (int k = 0; k < 8; k++) { loc[k] = band_ids[base + k]; cnt += loc[k]; }
    s_scan[tid] = cnt;
    __syncthreads();
    for (int off = 1; off < 256; off <<= 1) {
        int v = s_scan[tid];
        int w = (tid >= off) ? s_scan[tid - off] : 0;
        __syncthreads();
        s_scan[tid] = v + w;
        __syncthreads();
    }
    const int total = s_scan[255];
    int ones_before = s_scan[tid] - cnt;
#pragma unroll
    for (int k = 0; k < 8; k++) {
        int t = tid * 8 + k;
        int bid = loc[k];
        int pos = bid ? ones_before : (t - ones_before);
        g_dts[(b * LBn + bid) * Tn + pos] = dtime[b * Tn + t];
        ones_before += bid;
    }
    if (tid == 0) {
        g_cnt[b * LBn + 1] = total;
        g_cnt[b * LBn + 0] = Tn - total;
    }
}

// ---------------------------------------------------------------------------
// Main: one block (3 warps) per chain, layer-pipelined, named-barrier sync.
//   W0: layer-1 recurrence -> sH1 ring
//   W2: gx2 = Wih2 @ h1 -> sGX2 ring ; MLP on sH2 ; tail fill
//   W1: layer-2 recurrence -> sH2 ring
// ---------------------------------------------------------------------------
__global__ void __launch_bounds__(96, 4)
rnn_kernel(const float* __restrict__ zlast,
           const float* __restrict__ projW, const float* __restrict__ projB,
           const float* __restrict__ Wih,   const float* __restrict__ Whh,
           const float* __restrict__ bih,   const float* __restrict__ bhh,
           const float* __restrict__ mW1,   const float* __restrict__ mb1,
           const float* __restrict__ mW2,   const float* __restrict__ mb2,
           float* __restrict__ out) {
    const int kb = blockIdx.x & 1;
    const int b  = blockIdx.x >> 1;
    const int g  = threadIdx.x;
    const int lane = g & 31;
    const int warp = g >> 5;
    const int cid = b * LBn + kb;

    __shared__ __align__(16) float sDT[Tn];
    __shared__ __align__(16) float sH1[RD][CH][32];
    __shared__ __align__(16) float sGX2[RD][CH][96];
    __shared__ __align__(16) float sH2[RD][CH][32];
    __shared__ __align__(16) u64   sMW1p[16 * 32];
    __shared__ float sBase[32], sW[32], sZ[64];

    for (int i = g; i < Tn; i += 96) sDT[i] = g_dts[cid * Tn + i];
    if (g < 64) sZ[g] = zlast[b * Dn + g];
    for (int idx = g; idx < 16 * 32; idx += 96) {
        int k = idx >> 5, d = idx & 31;
        sMW1p[idx] = pack2(mW1[kb * 1024 + (2 * k) * 32 + d],
                           mW1[kb * 1024 + (2 * k + 1) * 32 + d]);
    }
    __syncthreads();

    const int n = g_cnt[cid];
    const int nch = (n + CH - 1) / CH;
    float* outp = out + (size_t)(kb * Bn + b) * Tn;
    const float s1 = -1.4426950408889634f;   // -log2(e)
    const float s2 = -2.8853900817779268f;   // -2*log2(e)
    const int l1 = (kb * Ln + 0) * Gn;
    const int l2 = (kb * Ln + 1) * Gn;

    if (warp == 0) {
        // -------- layer-1 recurrence --------
        u64 wr[16], wz[16], wn[16];
        loadrow(wr, &Whh[(l1 + lane) * DBn], s1);
        loadrow(wz, &Whh[(l1 + lane + 32) * DBn], s1);
        loadrow(wn, &Whh[(l1 + lane + 64) * DBn], s2);
        const float bhr = s1 * bhh[l1 + lane];
        const float bhz = s1 * bhh[l1 + lane + 32];
        const float bhn = s2 * bhh[l1 + lane + 64];

        float base = projB[kb * DBn + lane];
        float w = projW[(kb * (Dn + 1) + Dn) * DBn + lane];
#pragma unroll 8
        for (int i = 0; i < 64; i++) base += sZ[i] * projW[(kb * (Dn + 1) + i) * DBn + lane];
        sBase[lane] = base; sW[lane] = w;
        __syncwarp();

        float gbr, gbz, gbn, gwr, gwz, gwn;
        {
            float ar = bih[l1 + lane], cr = 0.f;
            float az = bih[l1 + lane + 32], cz = 0.f;
            float an = bih[l1 + lane + 64], cn = 0.f;
#pragma unroll 8
            for (int d = 0; d < 32; d++) {
                float wv = Wih[(l1 + lane) * DBn + d];
                ar += wv * sBase[d]; cr += wv * sW[d];
                wv = Wih[(l1 + lane + 32) * DBn + d];
                az += wv * sBase[d]; cz += wv * sW[d];
                wv = Wih[(l1 + lane + 64) * DBn + d];
                an += wv * sBase[d]; cn += wv * sW[d];
            }
            gbr = s1 * ar; gwr = s1 * cr;
            gbz = s1 * az; gwz = s1 * cz;
            gbn = s2 * an; gwn = s2 * cn;
        }

        float h1s = 0.f;
        u64 hp[16];
#pragma unroll
        for (int k = 0; k < 16; k++) hp[k] = 0ull;

        for (int c = 0; c < nch; c++) {
            const int slot = c & 1;
            if (c >= RD) bar_sync(B_S1 + slot);       // wait: W2 freed this slot
#pragma unroll
            for (int i = 0; i < CH; i++) {
                const float dt = sDT[c * CH + i];
                float ghr = bhr + dot32(wr, hp);
                float ghz = bhz + dot32(wz, hp);
                float ghn = bhn + dot32(wn, hp);
                float r  = rcpf(1.f + ex2f(fmaf(dt, gwr, gbr) + ghr));
                float z  = rcpf(1.f + ex2f(fmaf(dt, gwz, gbz) + ghz));
                float nn = fmaf(2.f, rcpf(1.f + ex2f(fmaf(r, ghn, fmaf(dt, gwn, gbn)))), -1.f);
                h1s = fmaf(z, h1s - nn, nn);
                sH1[slot][i][lane] = h1s;
                cbar();                                // warp-synchronous STS->LDS
                loadhp(hp, sH1[slot][i]);
            }
            membar_cta();
            bar_arrive(B_R1 + slot);                  // signal: sH1 chunk ready
        }
    } else if (warp == 1) {
        // -------- layer-2 recurrence --------
        u64 wr[16], wz[16], wn[16];
        loadrow(wr, &Whh[(l2 + lane) * DBn], s1);
        loadrow(wz, &Whh[(l2 + lane + 32) * DBn], s1);
        loadrow(wn, &Whh[(l2 + lane + 64) * DBn], s2);
        const float bhr = s1 * bhh[l2 + lane];
        const float bhz = s1 * bhh[l2 + lane + 32];
        const float bhn = s2 * bhh[l2 + lane + 64];

        float h2s = 0.f;
        u64 hp[16];
#pragma unroll
        for (int k = 0; k < 16; k++) hp[k] = 0ull;

        for (int c = 0; c < nch; c++) {
            const int slot = c & 1;
            bar_sync(B_R2 + slot);                    // wait: gx2 chunk ready
            if (c >= RD) bar_sync(B_S2 + slot);       // wait: W2 done with old sH2 slot
#pragma unroll
            for (int i = 0; i < CH; i++) {
                float gxr = sGX2[slot][i][lane];
                float gxz = sGX2[slot][i][lane + 32];
                float gxn = sGX2[slot][i][lane + 64];
                float ghr = bhr + dot32(wr, hp);
                float ghz = bhz + dot32(wz, hp);
                float ghn = bhn + dot32(wn, hp);
                float r  = rcpf(1.f + ex2f(gxr + ghr));
                float z  = rcpf(1.f + ex2f(gxz + ghz));
                float nn = fmaf(2.f, rcpf(1.f + ex2f(fmaf(r, ghn, gxn))), -1.f);
                h2s = fmaf(z, h2s - nn, nn);
                sH2[slot][i][lane] = h2s;
                cbar();
                loadhp(hp, sH2[slot][i]);
            }
            membar_cta();
            bar_arrive(B_R3 + slot);                  // signal: sH2 chunk ready (+ gx2 slot free)
        }
    } else {
        // -------- feedforward: gx2 producer + MLP consumer + tail --------
        u64 wr[16], wz[16], wn[16];
        loadrow(wr, &Wih[(l2 + lane) * DBn], s1);
        loadrow(wz, &Wih[(l2 + lane + 32) * DBn], s1);
        loadrow(wn, &Wih[(l2 + lane + 64) * DBn], s2);
        const float bir = s1 * bih[l2 + lane];
        const float biz = s1 * bih[l2 + lane + 32];
        const float bin = s2 * bih[l2 + lane + 64];
        const float mb1v = mb1[kb * DBn + lane];
        const float mw2v = mW2[kb * DBn + lane];
        const float mb2v = mb2[kb];
        float yl = 0.f;

        for (int c = 0; c < nch; c++) {
            const int slot = c & 1;
            bar_sync(B_R1 + slot);                    // wait: sH1 chunk ready
#pragma unroll
            for (int i = 0; i < CH; i++) {
                u64 hp[16];
                loadhp(hp, sH1[slot][i]);
                sGX2[slot][i][lane]      = bir + dot32(wr, hp);
                sGX2[slot][i][lane + 32] = biz + dot32(wz, hp);
                sGX2[slot][i][lane + 64] = bin + dot32(wn, hp);
            }
            membar_cta();
            bar_arrive(B_R2 + slot);                  // signal: gx2 ready
            bar_arrive(B_S1 + slot);                  // signal: sH1 slot free

            if (c >= 1) {
                const int cc = c - 1;
                const int ss = cc & 1;
                bar_sync(B_R3 + ss);                  // wait: sH2 chunk ready
#pragma unroll
                for (int i = 0; i < CH; i++) {
                    const int t = cc * CH + i;
                    u64 hp[16];
                    loadhp(hp, sH2[ss][i]);
                    u64 a0 = 0ull, a1 = 0ull;
#pragma unroll
                    for (int k = 0; k < 16; k += 2) {
                        a0 = ffma2(sMW1p[k * 32 + lane], hp[k], a0);
                        a1 = ffma2(sMW1p[(k + 1) * 32 + lane], hp[k + 1], a1);
                    }
                    float m = fmaxf(hsum(a0) + hsum(a1) + mb1v, 0.f);
                    float y = m * mw2v;
#pragma unroll
                    for (int off = 16; off > 0; off >>= 1) y += __shfl_xor_sync(0xffffffffu, y, off);
                    y += mb2v;
                    if (lane == 0 && t < n) outp[t] = y;
                    if (t == n - 1) yl = y;
                }
                bar_arrive(B_S2 + ss);                // signal: sH2 slot free
            }
        }
        if (nch >= 1) {
            const int cc = nch - 1;
            const int ss = cc & 1;
            bar_sync(B_R3 + ss);
#pragma unroll
            for (int i = 0; i < CH; i++) {
                const int t = cc * CH + i;
                u64 hp[16];
                loadhp(hp, sH2[ss][i]);
                u64 a0 = 0ull, a1 = 0ull;
#pragma unroll
                for (int k = 0; k < 16; k += 2) {
                    a0 = ffma2(sMW1p[k * 32 + lane], hp[k], a0);
                    a1 = ffma2(sMW1p[(k + 1) * 32 + lane], hp[k + 1], a1);
                }
                float m = fmaxf(hsum(a0) + hsum(a1) + mb1v, 0.f);
                float y = m * mw2v;
#pragma unroll
                for (int off = 16; off > 0; off >>= 1) y += __shfl_xor_sync(0xffffffffu, y, off);
                y += mb2v;
                if (lane == 0 && t < n) outp[t] = y;
                if (t == n - 1) yl = y;
            }
            bar_arrive(B_S2 + ss);
        }
        if (n == 0) {
            float m = fmaxf(mb1v, 0.f);
            float y = m * mw2v;
#pragma unroll
            for (int off = 16; off > 0; off >>= 1) y += __shfl_xor_sync(0xffffffffu, y, off);
            yl = y + mb2v;
        }
        for (int t = n + lane; t < Tn; t += 32) outp[t] = yl;
    }
}

extern "C" void kernel_launch(void* const* d_in, const int* in_sizes, int n_in,
                              void* d_out, int out_size) {
    const int*   band_ids = (const int*)  d_in[0];
    const float* dtime    = (const float*)d_in[1];
    const float* zlast    = (const float*)d_in[2];
    const float* projW    = (const float*)d_in[3];
    const float* projB    = (const float*)d_in[4];
    const float* Wih      = (const float*)d_in[5];
    const float* Whh      = (const float*)d_in[6];
    const float* bihp     = (const float*)d_in[7];
    const float* bhhp     = (const float*)d_in[8];
    const float* mW1      = (const float*)d_in[9];
    const float* mb1      = (const float*)d_in[10];
    const float* mW2      = (const float*)d_in[11];
    const float* mb2      = (const float*)d_in[12];

    prep_kernel<<<Bn, 256>>>(band_ids, dtime);
    rnn_kernel<<<Bn * LBn, 96>>>(zlast, projW, projB, Wih, Whh, bihp, bhhp,
                                 mW1, mb1, mW2, mb2, (float*)d_out);
}